// round 4
// baseline (speedup 1.0000x reference)
#include <cuda_runtime.h>
#include <cstdint>

// OpeningLoss2D: mean((x - grey_opening_2x2(x))^2) over [8,16,512,512] fp32.
// Separable: hmin2 -> vmin2 -> hmax2 -> vmax2 (scipy w=2, edge-replicate,
// er-index clamping on dilation).
//
// Warp-private pipelines: each warp owns a 128-col x 32-row strip and streams
// its rows (plus its own 2 halo scalars) GMEM->SMEM via a cp.async ring.
// Every thread reads only smem bytes its own cp.async wrote => NO block/warp
// barriers in the main loop; cross-lane halo via shuffles. One empty-or-real
// commit per iteration keeps group index == row index (tail-safe).

#define FULLMASK 0xffffffffu

static const int Hc = 512;
static const int Wc = 512;
static const int TR = 32;             // rows per tile
static const int NBLK = 2048;         // 128 slices * 16 row-tiles
static const int RING = 8;
static const int DEPTH = 6;           // cp.async groups in flight

__device__ float g_partials[NBLK];
__device__ unsigned int g_count = 0;

__device__ __forceinline__ void cp_async16(uint32_t saddr, const float* gaddr) {
    asm volatile("cp.async.cg.shared.global [%0], [%1], 16;\n"
                 :: "r"(saddr), "l"(gaddr));
}
__device__ __forceinline__ void cp_async4(uint32_t saddr, const float* gaddr) {
    asm volatile("cp.async.ca.shared.global [%0], [%1], 4;\n"
                 :: "r"(saddr), "l"(gaddr));
}
__device__ __forceinline__ void cp_commit() {
    asm volatile("cp.async.commit_group;\n" ::: "memory");
}
template <int N>
__device__ __forceinline__ void cp_wait() {
    asm volatile("cp.async.wait_group %0;\n" :: "n"(N) : "memory");
}

__global__ void __launch_bounds__(128, 10)
opening_kernel(const float* __restrict__ X, float* __restrict__ out) {
    __shared__ float ring[RING][Wc];      // 16 KB
    __shared__ float halo[RING][8];       // [slot][warp*2 + (0=left,1=right)]
    __shared__ float wsum[4];
    __shared__ bool amLast;

    const int t      = threadIdx.x;       // 0..127
    const int lane   = t & 31;
    const int warpId = t >> 5;
    const int tile   = blockIdx.x;        // 0..2047
    const int slice  = tile >> 4;         // 0..127
    const int r0     = (tile & 15) * TR;
    const float* S   = X + (size_t)slice * (Hc * Wc);
    const int c0     = t << 2;            // first owned column
    const int cs     = warpId << 7;       // warp strip start
    const bool lastT = (t == 127);        // owns col 511
    const bool isL0  = (lane == 0);
    const bool isL31 = (lane == 31);
    const int lcol   = max(cs - 1, 0);
    const int rcol   = min(cs + 128, Wc - 1);

    const uint32_t sring =
        (uint32_t)__cvta_generic_to_shared(&ring[0][0]) + (uint32_t)(c0 * 4);
    const uint32_t shalo =
        (uint32_t)__cvta_generic_to_shared(&halo[0][0]) +
        (uint32_t)((warpId * 2 + (isL31 ? 1 : 0)) * 4);

    // issue loads for pipeline step p: global row clamp(r0-1+p)
    #define ISSUE(p) do {                                                   \
        int _gr = min(max(r0 - 1 + (p), 0), Hc - 1);                        \
        const float* _rp = S + (size_t)_gr * Wc;                            \
        uint32_t _sl = (uint32_t)(((p) & (RING - 1)));                      \
        cp_async16(sring + _sl * (Wc * 4), _rp + c0);                       \
        if (isL0)  cp_async4(shalo + _sl * 32, _rp + lcol);                 \
        if (isL31) cp_async4(shalo + _sl * 32, _rp + rcol);                 \
    } while (0)

    #pragma unroll
    for (int p = 0; p < DEPTH; ++p) { ISSUE(p); cp_commit(); }

    float vprev[4], hm_prev[5], hM_prev[4];
    float acc = 0.f;

    #pragma unroll 2
    for (int p = 0; p <= TR + 1; ++p) {
        cp_wait<DEPTH - 1>();             // group p complete (1 group / iter)
        if (p + DEPTH <= TR + 1) ISSUE(p + DEPTH);
        cp_commit();                      // always commit: group idx tracks p

        const int slot = p & (RING - 1);
        float4 q = *reinterpret_cast<const float4*>(&ring[slot][c0]);
        float v0 = q.x, v1 = q.y, v2 = q.z, v3 = q.w;

        float L  = __shfl_up_sync(FULLMASK, v3, 1);
        float Rh = __shfl_down_sync(FULLMASK, v0, 1);
        if (isL0)  L  = halo[slot][warpId * 2];       // own cp.async data
        if (isL31) Rh = halo[slot][warpId * 2 + 1];   // own cp.async data

        float hm[5];
        hm[0] = fminf(L,  v0);
        hm[1] = fminf(v0, v1);
        hm[2] = fminf(v1, v2);
        hm[3] = fminf(v2, v3);
        hm[4] = fminf(v3, Rh);

        if (p >= 1) {
            float er[5];
            #pragma unroll
            for (int k = 0; k < 5; ++k) er[k] = fminf(hm_prev[k], hm[k]);
            float hM[4];
            #pragma unroll
            for (int k = 0; k < 4; ++k) hM[k] = fmaxf(er[k], er[k + 1]);
            if (lastT) hM[3] = er[3];                 // er-col clamp at W-1
            if (r0 + p - 1 >= Hc) {                   // er-row clamp at H-1
                #pragma unroll
                for (int k = 0; k < 4; ++k) hM[k] = hM_prev[k];
            }
            if (p >= 2) {
                #pragma unroll
                for (int k = 0; k < 4; ++k) {
                    float s = fmaxf(hM_prev[k], hM[k]);
                    float d = vprev[k] - s;
                    acc = fmaf(d, d, acc);
                }
            }
            #pragma unroll
            for (int k = 0; k < 4; ++k) hM_prev[k] = hM[k];
        }

        #pragma unroll
        for (int k = 0; k < 5; ++k) hm_prev[k] = hm[k];
        vprev[0] = v0; vprev[1] = v1; vprev[2] = v2; vprev[3] = v3;
    }
    #undef ISSUE

    // Warp reduce
    #pragma unroll
    for (int off = 16; off; off >>= 1)
        acc += __shfl_down_sync(FULLMASK, acc, off);
    if (lane == 0) wsum[warpId] = acc;
    __syncthreads();
    if (t == 0) {
        float s = wsum[0] + wsum[1] + wsum[2] + wsum[3];
        g_partials[blockIdx.x] = s;
        __threadfence();
        unsigned int old = atomicAdd(&g_count, 1u);
        amLast = (old == (unsigned)(NBLK - 1));
    }
    __syncthreads();

    if (amLast) {
        __shared__ float sh[128];
        float s = 0.f;
        for (int i = t; i < NBLK; i += 128) s += g_partials[i];
        sh[t] = s;
        __syncthreads();
        #pragma unroll
        for (int off = 64; off; off >>= 1) {
            if (t < off) sh[t] += sh[t + off];
            __syncthreads();
        }
        if (t == 0) {
            out[0] = sh[0] * (1.0f / 33554432.0f);  // mean over 8*16*512*512
            g_count = 0;                            // deterministic graph replays
        }
    }
}

extern "C" void kernel_launch(void* const* d_in, const int* in_sizes, int n_in,
                              void* d_out, int out_size) {
    const float* X = (const float*)d_in[0];
    opening_kernel<<<NBLK, 128>>>(X, (float*)d_out);
}

// round 5
// speedup vs baseline: 1.3161x; 1.3161x over previous
#include <cuda_runtime.h>
#include <cstdint>
#include <math_constants.h>

// OpeningLoss2D: mean((x - grey_opening_2x2(x))^2) over [8,16,512,512] fp32.
// Block-wide 512-col x 64-row tile, cp.async ring of 8 rows (2-row groups,
// 3 groups in flight). 2 rows per pipeline step => half the barriers/waits/
// commits. Smem rows padded with a -inf sentinel at col 512 so the W-1
// dilation clamp needs no per-row predicate. First/last steps peeled so the
// hot loop is branch-free.

#define FULLMASK 0xffffffffu

static const int Hc = 512;
static const int Wc = 512;
static const int TR = 64;
static const int NBLK = 1024;          // 128 slices * 8 row-tiles
static const int ROWP = 516;           // padded row (col 512 = -inf sentinel)
static const int DEPTH = 3;            // 2-row groups in flight (6 rows)

__device__ float g_partials[NBLK];
__device__ unsigned int g_count = 0;

__device__ __forceinline__ void cp_async16(uint32_t saddr, const float* gaddr) {
    asm volatile("cp.async.cg.shared.global [%0], [%1], 16;\n"
                 :: "r"(saddr), "l"(gaddr));
}
__device__ __forceinline__ void cp_commit() {
    asm volatile("cp.async.commit_group;\n" ::: "memory");
}
template <int N>
__device__ __forceinline__ void cp_wait() {
    asm volatile("cp.async.wait_group %0;\n" :: "n"(N) : "memory");
}

__global__ void __launch_bounds__(128, 8)
opening_kernel(const float* __restrict__ X, float* __restrict__ out) {
    __shared__ float ring[8][ROWP];       // ~16.5 KB
    __shared__ float wsum[4];
    __shared__ bool amLast;

    const int t      = threadIdx.x;       // 0..127
    const int lane   = t & 31;
    const int warpId = t >> 5;
    const int tile   = blockIdx.x;        // 0..1023
    const int slice  = tile >> 3;         // 0..127
    const int r0     = (tile & 7) * TR;
    const float* S   = X + (size_t)slice * (Hc * Wc);
    const int c0     = t << 2;
    const bool isL0  = (lane == 0);
    const bool isL31 = (lane == 31);
    const int lcol   = max(c0 - 1, 0);
    const int rcol   = c0 + 4;            // t==127 -> 512 (-inf pad)

    if (t < 8) ring[t][512] = -CUDART_INF_F;   // sentinel, never overwritten

    const uint32_t sring =
        (uint32_t)__cvta_generic_to_shared(&ring[0][0]) + (uint32_t)(c0 * 4);

    // group g covers pipeline rows 2g, 2g+1 ; row p holds x row clamp(r0-1+p)
    #define ISSUE2(g) do {                                                    \
        int _p0 = 2 * (g);                                                    \
        int _g0 = min(max(r0 - 1 + _p0, 0), Hc - 1);                          \
        int _g1 = min(r0 + _p0, Hc - 1);                                      \
        cp_async16(sring + (uint32_t)(((_p0)     & 7) * (ROWP * 4)),          \
                   S + (size_t)_g0 * Wc + c0);                                \
        cp_async16(sring + (uint32_t)(((_p0 + 1) & 7) * (ROWP * 4)),          \
                   S + (size_t)_g1 * Wc + c0);                                \
    } while (0)

    #define LOADROW(pp) \
        const float* _row = ring[(pp) & 7];                                   \
        float4 _q = *reinterpret_cast<const float4*>(_row + c0);              \
        float _L = __shfl_up_sync(FULLMASK, _q.w, 1);                         \
        float _R = __shfl_down_sync(FULLMASK, _q.x, 1);                       \
        if (isL0)  _L = _row[lcol];                                           \
        if (isL31) _R = _row[rcol];                                           \
        float _h0 = fminf(_L,  _q.x), _h1 = fminf(_q.x, _q.y);                \
        float _h2 = fminf(_q.y, _q.z), _h3 = fminf(_q.z, _q.w);               \
        float _h4 = fminf(_q.w, _R);

    #define FULLROW(pp) do {                                                  \
        LOADROW(pp)                                                            \
        float _e0 = fminf(hp0,_h0), _e1 = fminf(hp1,_h1), _e2 = fminf(hp2,_h2);\
        float _e3 = fminf(hp3,_h3), _e4 = fminf(hp4,_h4);                      \
        float _M0 = fmaxf(_e0,_e1), _M1 = fmaxf(_e1,_e2);                      \
        float _M2 = fmaxf(_e2,_e3), _M3 = fmaxf(_e3,_e4);                      \
        float _s0 = fmaxf(Mp0,_M0), _s1 = fmaxf(Mp1,_M1);                      \
        float _s2 = fmaxf(Mp2,_M2), _s3 = fmaxf(Mp3,_M3);                      \
        float _d0 = xp0 - _s0, _d1 = xp1 - _s1;                                \
        float _d2 = xp2 - _s2, _d3 = xp3 - _s3;                                \
        acc0 = fmaf(_d0,_d0,acc0); acc1 = fmaf(_d1,_d1,acc1);                  \
        acc0 = fmaf(_d2,_d2,acc0); acc1 = fmaf(_d3,_d3,acc1);                  \
        hp0=_h0; hp1=_h1; hp2=_h2; hp3=_h3; hp4=_h4;                           \
        Mp0=_M0; Mp1=_M1; Mp2=_M2; Mp3=_M3;                                    \
        xp0=_q.x; xp1=_q.y; xp2=_q.z; xp3=_q.w;                                \
    } while (0)

    float hp0, hp1, hp2, hp3, hp4;
    float Mp0, Mp1, Mp2, Mp3;
    float xp0, xp1, xp2, xp3;
    float acc0 = 0.f, acc1 = 0.f;

    #pragma unroll
    for (int g = 0; g < DEPTH; ++g) { ISSUE2(g); cp_commit(); }

    // step 0 (rows 0,1) peeled: no er at p=0, no smooth at p=1
    cp_wait<DEPTH - 1>();
    __syncthreads();
    ISSUE2(DEPTH);
    cp_commit();
    {   LOADROW(0)
        hp0=_h0; hp1=_h1; hp2=_h2; hp3=_h3; hp4=_h4;
    }
    {   LOADROW(1)
        float _e0 = fminf(hp0,_h0), _e1 = fminf(hp1,_h1), _e2 = fminf(hp2,_h2);
        float _e3 = fminf(hp3,_h3), _e4 = fminf(hp4,_h4);
        Mp0 = fmaxf(_e0,_e1); Mp1 = fmaxf(_e1,_e2);
        Mp2 = fmaxf(_e2,_e3); Mp3 = fmaxf(_e3,_e4);
        hp0=_h0; hp1=_h1; hp2=_h2; hp3=_h3; hp4=_h4;
        xp0=_q.x; xp1=_q.y; xp2=_q.z; xp3=_q.w;
    }

    // hot loop: steps 1..31, branch/predicate-free rows
    #pragma unroll 2
    for (int s = 1; s <= 31; ++s) {
        cp_wait<DEPTH - 1>();
        __syncthreads();
        if (s + DEPTH <= 32) ISSUE2(s + DEPTH);
        cp_commit();                       // always: group idx tracks step
        FULLROW(2 * s);
        FULLROW(2 * s + 1);
    }

    // step 32 (rows 64,65) peeled: bottom-boundary handling
    cp_wait<0>();
    __syncthreads();
    FULLROW(64);
    if (r0 + TR >= Hc) {
        // er row 512 doesn't exist: smooth(511) = hM(511) = Mp
        float _d0 = xp0 - Mp0, _d1 = xp1 - Mp1;
        float _d2 = xp2 - Mp2, _d3 = xp3 - Mp3;
        acc0 = fmaf(_d0,_d0,acc0); acc1 = fmaf(_d1,_d1,acc1);
        acc0 = fmaf(_d2,_d2,acc0); acc1 = fmaf(_d3,_d3,acc1);
    } else {
        FULLROW(65);
    }
    #undef ISSUE2
    #undef LOADROW
    #undef FULLROW

    float acc = acc0 + acc1;
    #pragma unroll
    for (int off = 16; off; off >>= 1)
        acc += __shfl_down_sync(FULLMASK, acc, off);
    if (lane == 0) wsum[warpId] = acc;
    __syncthreads();
    if (t == 0) {
        float s = wsum[0] + wsum[1] + wsum[2] + wsum[3];
        g_partials[blockIdx.x] = s;
        __threadfence();
        unsigned int old = atomicAdd(&g_count, 1u);
        amLast = (old == (unsigned)(NBLK - 1));
    }
    __syncthreads();

    if (amLast) {
        __shared__ float sh[128];
        float s = 0.f;
        for (int i = t; i < NBLK; i += 128) s += g_partials[i];
        sh[t] = s;
        __syncthreads();
        #pragma unroll
        for (int off = 64; off; off >>= 1) {
            if (t < off) sh[t] += sh[t + off];
            __syncthreads();
        }
        if (t == 0) {
            out[0] = sh[0] * (1.0f / 33554432.0f);  // mean over 8*16*512*512
            g_count = 0;                            // deterministic replays
        }
    }
}

extern "C" void kernel_launch(void* const* d_in, const int* in_sizes, int n_in,
                              void* d_out, int out_size) {
    const float* X = (const float*)d_in[0];
    opening_kernel<<<NBLK, 128>>>(X, (float*)d_out);
}